// round 7
// baseline (speedup 1.0000x reference)
#include <cuda_runtime.h>
#include <cstdint>

#define Bb 256
#define Tt 512

__device__ uint2 g_keys[1024];
__device__ float g_gum[1024][2560];
__device__ int   g_act2[Tt * Bb];
__device__ float g_gi[(size_t)Bb * Tt * 384];

__device__ __forceinline__ void tf2x32(uint32_t k0, uint32_t k1,
                                       uint32_t x0, uint32_t x1,
                                       uint32_t &o0, uint32_t &o1) {
  uint32_t k2 = k0 ^ k1 ^ 0x1BD11BDAu;
#define R_(r) { x0 += x1; x1 = (x1 << (r)) | (x1 >> (32 - (r))); x1 ^= x0; }
  x0 += k0; x1 += k1;
  R_(13) R_(15) R_(26) R_(6)  x0 += k1; x1 += k2 + 1u;
  R_(17) R_(29) R_(16) R_(24) x0 += k2; x1 += k0 + 2u;
  R_(13) R_(15) R_(26) R_(6)  x0 += k0; x1 += k1 + 3u;
  R_(17) R_(29) R_(16) R_(24) x0 += k1; x1 += k2 + 4u;
  R_(13) R_(15) R_(26) R_(6)  x0 += k2; x1 += k0 + 5u;
#undef R_
  o0 = x0; o1 = x1;
}

// float-precision gumbel: perturbation vs JAX ~2e-7, argmax margins ~1e-4.
__device__ __forceinline__ float b2g(uint32_t bits) {
  float f = __uint_as_float((bits >> 9) | 0x3f800000u) - 1.0f;
  float u = fmaxf(f, 1.17549435e-38f);
  return -logf(-logf(u));
}

__device__ __forceinline__ float sigm(float x) { return 1.0f / (1.0f + expf(-x)); }

__global__ void k_keys() {
  int j = blockIdx.x * 256 + threadIdx.x;
  if (j >= 1024) return;
  uint32_t o0, o1;
  tf2x32(0u, 42u, 0u, (uint32_t)j, o0, o1);
  g_keys[j] = make_uint2(o0, o1);
}

__global__ void k_gum() {
  int j = blockIdx.x;
  uint2 key = g_keys[j];
  for (int p = threadIdx.x; p < 2560; p += 256) {
    uint32_t o0, o1;
    tf2x32(key.x, key.y, 0u, (uint32_t)p, o0, o1);
    g_gum[j][p] = b2g(o0 ^ o1);
  }
}

// gi GEMM: grid (1024,3), 256 thr, 128x128 tile, 8x8 micro-tile.
__global__ __launch_bounds__(256) void k_gi(const float* __restrict__ x,
                                            const float* __restrict__ wih,
                                            const float* __restrict__ bih,
                                            const float* __restrict__ bhh) {
  extern __shared__ float sm[];
  float* xs = sm;               // 128 x 132 (m-major)
  float* ws = xs + 128 * 132;   // 128 x 132 (k-major, transposed w)
  int tid = threadIdx.x;
  size_t m0 = (size_t)blockIdx.x * 128;
  int n0 = blockIdx.y * 128;
  int mr = tid >> 1, hl = tid & 1;
  {
    const float4* src = (const float4*)(x + (m0 + mr) * 128 + hl * 64);
    float4* dst = (float4*)(xs + mr * 132 + hl * 64);
#pragma unroll
    for (int i = 0; i < 16; i++) dst[i] = src[i];
  }
  {
    const float4* src = (const float4*)(wih + (size_t)(n0 + mr) * 128 + hl * 64);
#pragma unroll
    for (int i = 0; i < 16; i++) {
      float4 v = src[i];
      int kb = hl * 64 + i * 4;
      ws[(kb + 0) * 132 + mr] = v.x; ws[(kb + 1) * 132 + mr] = v.y;
      ws[(kb + 2) * 132 + mr] = v.z; ws[(kb + 3) * 132 + mr] = v.w;
    }
  }
  int tx = tid & 15, ty = tid >> 4;
  float bv[8];
#pragma unroll
  for (int j = 0; j < 8; j++) {
    int g = n0 + tx * 8 + j;
    bv[j] = bih[g] + (g < 256 ? bhh[g] : 0.0f);
  }
  __syncthreads();

  float acc[64];
#pragma unroll
  for (int i = 0; i < 8; i++)
#pragma unroll
    for (int j = 0; j < 8; j++) acc[i * 8 + j] = bv[j];
  const float* xrow = xs + ty * 8 * 132;
#pragma unroll 2
  for (int kk = 0; kk < 128; kk += 4) {
    float4 a4[8];
#pragma unroll
    for (int i = 0; i < 8; i++) a4[i] = *(const float4*)(xrow + i * 132 + kk);
#pragma unroll
    for (int dk = 0; dk < 4; dk++) {
      float4 bl = *(const float4*)(ws + (kk + dk) * 132 + tx * 8);
      float4 bh = *(const float4*)(ws + (kk + dk) * 132 + tx * 8 + 4);
#pragma unroll
      for (int i = 0; i < 8; i++) {
        float av = (dk == 0) ? a4[i].x : (dk == 1) ? a4[i].y : (dk == 2) ? a4[i].z : a4[i].w;
        acc[i*8+0] += av * bl.x; acc[i*8+1] += av * bl.y;
        acc[i*8+2] += av * bl.z; acc[i*8+3] += av * bl.w;
        acc[i*8+4] += av * bh.x; acc[i*8+5] += av * bh.y;
        acc[i*8+6] += av * bh.z; acc[i*8+7] += av * bh.w;
      }
    }
  }
#pragma unroll
  for (int i = 0; i < 8; i++) {
    float* dst = g_gi + (m0 + ty * 8 + i) * 384 + n0 + tx * 8;
    *(float4*)(dst)     = make_float4(acc[i*8+0], acc[i*8+1], acc[i*8+2], acc[i*8+3]);
    *(float4*)(dst + 4) = make_float4(acc[i*8+4], acc[i*8+5], acc[i*8+6], acc[i*8+7]);
  }
}

__global__ __launch_bounds__(128) void k_act2(const float* __restrict__ x,
                                              const float* __restrict__ w1,
                                              const float* __restrict__ b1,
                                              const float* __restrict__ w2,
                                              const float* __restrict__ b2) {
  extern __shared__ float sm[];
  float* xs  = sm;
  float* w1s = xs + 128 * 132;
  float* w2s = w1s + 64 * 128;
  float* b1s = w2s + 640;
  float* b2s = b1s + 64;
  int tid = threadIdx.x;
  size_t row0 = (size_t)blockIdx.x * 128;
  const float4* xg = (const float4*)(x + row0 * 128);
  for (int i = tid; i < 128 * 32; i += 128) {
    int r = i >> 5, c = i & 31;
    ((float4*)(xs + r * 132))[c] = xg[i];
  }
  for (int i = tid; i < 64 * 32; i += 128) ((float4*)w1s)[i] = ((const float4*)w1)[i];
  for (int i = tid; i < 640; i += 128) w2s[i] = w2[i];
  if (tid < 64) b1s[tid] = b1[tid];
  if (tid < 10) b2s[tid] = b2[tid];
  __syncthreads();
  float acc[64];
#pragma unroll
  for (int u = 0; u < 64; u++) acc[u] = b1s[u];
  const float4* xr = (const float4*)(xs + tid * 132);
  for (int c = 0; c < 32; c++) {
    float4 xv = xr[c];
#pragma unroll
    for (int u = 0; u < 64; u++) {
      float4 wv = ((const float4*)w1s)[u * 32 + c];
      acc[u] += xv.x * wv.x + xv.y * wv.y + xv.z * wv.z + xv.w * wv.w;
    }
  }
#pragma unroll
  for (int u = 0; u < 64; u++) acc[u] = tanhf(acc[u]);
  size_t row = row0 + tid;
  int b = (int)(row >> 9), t = (int)(row & 511);
  const float* gg = g_gum[2 * t + 1] + b * 10;
  float best = -1e30f; int bi = 0;
#pragma unroll
  for (int a = 0; a < 10; a++) {
    float lg = b2s[a];
#pragma unroll
    for (int u = 0; u < 64; u++) lg += acc[u] * w2s[a * 64 + u];
    float v = lg + gg[a];
    if (v > best) { best = v; bi = a; }
  }
  g_act2[t * 256 + b] = bi;
}

// recurrent: 128 CTAs x 512 thr, 4-way k split.
// tid: d = tid&127, q = tid>>7. Owners tid<256: (bb=q, d).
__global__ __launch_bounds__(512, 1) void k_recur(const int* __restrict__ mask,
                                                  const float* __restrict__ whh,
                                                  const float* __restrict__ bhh,
                                                  const float* __restrict__ a1w1,
                                                  const float* __restrict__ a1b1,
                                                  const float* __restrict__ a1w2,
                                                  const float* __restrict__ a1b2,
                                                  float* __restrict__ out) {
  extern __shared__ float sm[];
  float* wsp  = sm;                  // 384 x 132 padded w_hh
  float* wt   = wsp + 384 * 132;     // [2][128]
  float* ps   = wt + 256;            // [zb][kq][u] = 512
  float* exch = ps + 512;            // [q][b][g][d] = 3072
  float* gsm  = exch + 3072;         // [2][20] gumbel double-buffer
  float* bsm  = gsm + 40;            // b2 (10, pad 12)
  int*  asm2  = (int*)(bsm + 12);    // [2][2] act2 double-buffer
  int*  ais   = asm2 + 4;            // a1[2], a2[2]

  int tid = threadIdx.x;
  int d = tid & 127, q = tid >> 7;
  int wid = tid >> 5, lane = tid & 31;
  int b0 = blockIdx.x * 2;
  int bb = q & 1;
  int bg = b0 + bb;
  bool owner = (tid < 256);
  float* outh = out + (size_t)Bb * 128;

  for (int i = tid; i < 384 * 128; i += 512)
    wsp[(i >> 7) * 132 + (i & 127)] = whh[i];

  // zarg weights in regs: thread (u=tid&63, kq=(tid>>6)&3, zb=tid>>8)
  float w1r[32];
  {
    int u = tid & 63, kq = (tid >> 6) & 3;
    const float4* src = (const float4*)(a1w1 + u * 128 + kq * 32);
#pragma unroll
    for (int k = 0; k < 8; k++) {
      float4 v = src[k];
      w1r[4*k] = v.x; w1r[4*k+1] = v.y; w1r[4*k+2] = v.z; w1r[4*k+3] = v.w;
    }
  }
  float bhn = bhh[256 + d];
  float w2a[10], w2b[10], b1a = 0.0f, b1b = 0.0f;
#pragma unroll
  for (int a = 0; a < 10; a++) { w2a[a] = 0.0f; w2b[a] = 0.0f; }
  if (wid < 2) {
    b1a = a1b1[lane]; b1b = a1b1[lane + 32];
#pragma unroll
    for (int a = 0; a < 10; a++) {
      w2a[a] = a1w2[a * 64 + lane];
      w2b[a] = a1w2[a * 64 + lane + 32];
    }
  }
  if (tid < 10) bsm[tid] = a1b2[tid];

  float h = 0.0f, buf[10];
#pragma unroll
  for (int s9 = 0; s9 < 10; s9++) buf[s9] = 0.0f;

  if (owner) {
    size_t rr = ((size_t)bg * 512) * 384;
    float gir = g_gi[rr + d], giz = g_gi[rr + 128 + d], gin = g_gi[rr + 256 + d];
    float r = sigm(gir), z = sigm(giz);
    h = (1.0f - z) * tanhf(gin + r * bhn);
    outh[((size_t)bg * 512) * 128 + d] = h;
  }
  // prefetch t=1 gumbel/act2 into smem buffer 1
  if (tid < 20)       gsm[20 + tid] = g_gum[2][(b0 + tid / 10) * 10 + tid % 10];
  else if (tid < 22)  asm2[2 + tid - 20] = g_act2[256 + b0 + (tid - 20)];
  __syncthreads();

  for (int t = 1; t < 512; t++) {
    int cur = t & 1, nxt = cur ^ 1;
    float gir = 0, giz = 0, gin = 0;
    if (owner) {
      size_t rg = ((size_t)bg * 512 + t) * 384;
      gir = g_gi[rg + d]; giz = g_gi[rg + 128 + d]; gin = g_gi[rg + 256 + d];
      float s = h;
#pragma unroll
      for (int s9 = 0; s9 < 9; s9++) { buf[s9] = buf[s9 + 1]; s += buf[s9]; }
      buf[9] = h;
      wt[bb * 128 + d] = s * 0.1f;
    }
    __syncthreads();                                  // A
    {
      int zb = tid >> 8, kq = (tid >> 6) & 3;
      const float4* mv = (const float4*)(wt + zb * 128 + kq * 32);
      float p = 0.0f;
#pragma unroll
      for (int k = 0; k < 8; k++) {
        float4 m = mv[k];
        p += m.x*w1r[4*k] + m.y*w1r[4*k+1] + m.z*w1r[4*k+2] + m.w*w1r[4*k+3];
      }
      ps[tid] = p;
    }
    if (t < 511) {
      if (tid < 20)
        gsm[nxt * 20 + tid] = g_gum[2 * (t + 1)][(b0 + tid / 10) * 10 + tid % 10];
      else if (tid < 22)
        asm2[nxt * 2 + tid - 20] = g_act2[(t + 1) * 256 + b0 + (tid - 20)];
    }
    __syncthreads();                                  // B
    if (wid < 2) {
      float sA = 0.0f, sB = 0.0f;
#pragma unroll
      for (int kq = 0; kq < 4; kq++) {
        sA += ps[wid * 256 + kq * 64 + lane];
        sB += ps[wid * 256 + kq * 64 + 32 + lane];
      }
      float zA = tanhf(sA + b1a), zB = tanhf(sB + b1b);
      float lp[10];
#pragma unroll
      for (int a = 0; a < 10; a++) lp[a] = zA * w2a[a] + zB * w2b[a];
#pragma unroll
      for (int off = 16; off > 0; off >>= 1)
#pragma unroll
        for (int a = 0; a < 10; a++) lp[a] += __shfl_down_sync(0xffffffffu, lp[a], off);
      if (lane == 0) {
        float best = -1e30f; int bi = 0;
#pragma unroll
        for (int a = 0; a < 10; a++) {
          float v = lp[a] + bsm[a] + gsm[cur * 20 + wid * 10 + a];
          if (v > best) { best = v; bi = a; }
        }
        ais[wid] = bi; ais[2 + wid] = asm2[cur * 2 + wid];
      }
    }
    __syncthreads();                                  // C
    float wtd = 0.0f;
    if (owner) {
      int aa = ais[bb], a2 = ais[2 + bb];
      float sa = buf[0], sb2 = buf[0];
#pragma unroll
      for (int s9 = 1; s9 < 10; s9++) {
        if (aa == s9) sa = buf[s9];
        if (a2 == s9) sb2 = buf[s9];
      }
      wtd = 0.25f * (sa + sb2) + 0.5f * h;
      wt[bb * 128 + d] = wtd;
    }
    __syncthreads();                                  // D
    {
      int k0 = q * 32;
      const float4* r0 = (const float4*)(wsp + d * 132 + k0);
      const float4* r1 = (const float4*)(wsp + (d + 128) * 132 + k0);
      const float4* r2 = (const float4*)(wsp + (d + 256) * 132 + k0);
      const float4* v0 = (const float4*)(wt + k0);
      const float4* v1 = (const float4*)(wt + 128 + k0);
      float a00 = 0, a01 = 0, a02 = 0, a10 = 0, a11 = 0, a12 = 0;
#pragma unroll
      for (int c = 0; c < 8; c++) {
        float4 wr = r0[c], wz = r1[c], wn = r2[c];
        float4 x0 = v0[c], x1 = v1[c];
        a00 += wr.x*x0.x + wr.y*x0.y + wr.z*x0.z + wr.w*x0.w;
        a01 += wz.x*x0.x + wz.y*x0.y + wz.z*x0.z + wz.w*x0.w;
        a02 += wn.x*x0.x + wn.y*x0.y + wn.z*x0.z + wn.w*x0.w;
        a10 += wr.x*x1.x + wr.y*x1.y + wr.z*x1.z + wr.w*x1.w;
        a11 += wz.x*x1.x + wz.y*x1.y + wz.z*x1.z + wz.w*x1.w;
        a12 += wn.x*x1.x + wn.y*x1.y + wn.z*x1.z + wn.w*x1.w;
      }
      exch[((q * 2 + 0) * 3 + 0) * 128 + d] = a00;
      exch[((q * 2 + 0) * 3 + 1) * 128 + d] = a01;
      exch[((q * 2 + 0) * 3 + 2) * 128 + d] = a02;
      exch[((q * 2 + 1) * 3 + 0) * 128 + d] = a10;
      exch[((q * 2 + 1) * 3 + 1) * 128 + d] = a11;
      exch[((q * 2 + 1) * 3 + 2) * 128 + d] = a12;
    }
    __syncthreads();                                  // E
    if (owner) {
      float gr = 0, gz = 0, gn = 0;
#pragma unroll
      for (int qq = 0; qq < 4; qq++) {
        gr += exch[((qq * 2 + bb) * 3 + 0) * 128 + d];
        gz += exch[((qq * 2 + bb) * 3 + 1) * 128 + d];
        gn += exch[((qq * 2 + bb) * 3 + 2) * 128 + d];
      }
      float r = sigm(gir + gr), z = sigm(giz + gz);
      float n = tanhf(gin + r * (gn + bhn));
      h = (1.0f - z) * n + z * wtd;
      outh[((size_t)bg * 512 + t) * 128 + d] = h;
    }
  }

  __syncthreads();
  if (owner) {
    int cnt = 0;
    for (int t2 = d; t2 < 512; t2 += 128) cnt += mask[bg * 512 + t2];
    ps[tid] = (float)cnt;
  }
  __syncthreads();
  if (tid < 2) {
    int s = 0;
    for (int i = 0; i < 128; i++) s += (int)ps[tid * 128 + i];
    ais[tid] = s - 1;
  }
  __syncthreads();
  if (owner) {
    int li = ais[bb];
    out[bg * 128 + d] = outh[((size_t)bg * 512 + li) * 128 + d];
  }
}

extern "C" void kernel_launch(void* const* d_in, const int* in_sizes, int n_in,
                              void* d_out, int out_size) {
  const float* x    = (const float*)d_in[0];
  const int*   mask = (const int*)d_in[1];
  const float* wih  = (const float*)d_in[2];
  const float* whh  = (const float*)d_in[3];
  const float* bih  = (const float*)d_in[4];
  const float* bhh  = (const float*)d_in[5];
  const float* a1w1 = (const float*)d_in[6];
  const float* a1b1 = (const float*)d_in[7];
  const float* a1w2 = (const float*)d_in[8];
  const float* a1b2 = (const float*)d_in[9];
  const float* a2w1 = (const float*)d_in[10];
  const float* a2b1 = (const float*)d_in[11];
  const float* a2w2 = (const float*)d_in[12];
  const float* a2b2 = (const float*)d_in[13];
  float* out = (float*)d_out;

  const int smem_gi = 2 * 128 * 132 * 4;
  const int smem_a2 = (128 * 132 + 64 * 128 + 640 + 64 + 16) * 4;
  const int smem_rc = (384 * 132 + 256 + 512 + 3072 + 40 + 12) * 4 + 32;

  cudaFuncSetAttribute(k_gi,    cudaFuncAttributeMaxDynamicSharedMemorySize, smem_gi);
  cudaFuncSetAttribute(k_act2,  cudaFuncAttributeMaxDynamicSharedMemorySize, smem_a2);
  cudaFuncSetAttribute(k_recur, cudaFuncAttributeMaxDynamicSharedMemorySize, smem_rc);

  k_keys<<<4, 256>>>();
  k_gum<<<1024, 256>>>();
  k_act2<<<1024, 128, smem_a2>>>(x, a2w1, a2b1, a2w2, a2b2);
  k_gi<<<dim3(1024, 3), 256, smem_gi>>>(x, wih, bih, bhh);
  k_recur<<<128, 512, smem_rc>>>(mask, whh, bhh, a1w1, a1b1, a1w2, a1b2, out);
}

// round 8
// speedup vs baseline: 1.1302x; 1.1302x over previous
#include <cuda_runtime.h>
#include <cstdint>

#define Bb 256
#define Tt 512

__device__ uint2 g_keys[1024];
__device__ float g_gum[1024][2560];
__device__ int   g_act2[Tt * Bb];
__device__ float g_gi[(size_t)Bb * Tt * 384];

__device__ __forceinline__ void tf2x32(uint32_t k0, uint32_t k1,
                                       uint32_t x0, uint32_t x1,
                                       uint32_t &o0, uint32_t &o1) {
  uint32_t k2 = k0 ^ k1 ^ 0x1BD11BDAu;
#define R_(r) { x0 += x1; x1 = (x1 << (r)) | (x1 >> (32 - (r))); x1 ^= x0; }
  x0 += k0; x1 += k1;
  R_(13) R_(15) R_(26) R_(6)  x0 += k1; x1 += k2 + 1u;
  R_(17) R_(29) R_(16) R_(24) x0 += k2; x1 += k0 + 2u;
  R_(13) R_(15) R_(26) R_(6)  x0 += k0; x1 += k1 + 3u;
  R_(17) R_(29) R_(16) R_(24) x0 += k1; x1 += k2 + 4u;
  R_(13) R_(15) R_(26) R_(6)  x0 += k2; x1 += k0 + 5u;
#undef R_
  o0 = x0; o1 = x1;
}

__device__ __forceinline__ float b2g(uint32_t bits) {
  float f = __uint_as_float((bits >> 9) | 0x3f800000u) - 1.0f;
  float u = fmaxf(f, 1.17549435e-38f);
  return -logf(-logf(u));
}

__device__ __forceinline__ float sigm(float x) { return 1.0f / (1.0f + expf(-x)); }

// packed dual-FMA: {a.lo*b.lo+c.lo, a.hi*b.hi+c.hi}
__device__ __forceinline__ void f2(unsigned long long &c,
                                   unsigned long long a, unsigned long long b) {
  asm("fma.rn.f32x2 %0, %1, %2, %0;" : "+l"(c) : "l"(a), "l"(b));
}
__device__ __forceinline__ float hsum(unsigned long long a) {
  return __uint_as_float((unsigned)a) + __uint_as_float((unsigned)(a >> 32));
}

__global__ void k_keys() {
  int j = blockIdx.x * 256 + threadIdx.x;
  if (j >= 1024) return;
  uint32_t o0, o1;
  tf2x32(0u, 42u, 0u, (uint32_t)j, o0, o1);
  g_keys[j] = make_uint2(o0, o1);
}

__global__ void k_gum() {
  int j = blockIdx.x;
  uint2 key = g_keys[j];
  for (int p = threadIdx.x; p < 2560; p += 256) {
    uint32_t o0, o1;
    tf2x32(key.x, key.y, 0u, (uint32_t)p, o0, o1);
    g_gum[j][p] = b2g(o0 ^ o1);
  }
}

// gi GEMM: grid (1024,3), 256 thr, 128x128 tile, 8x8 micro-tile (unchanged).
__global__ __launch_bounds__(256) void k_gi(const float* __restrict__ x,
                                            const float* __restrict__ wih,
                                            const float* __restrict__ bih,
                                            const float* __restrict__ bhh) {
  extern __shared__ float sm[];
  float* xs = sm;
  float* ws = xs + 128 * 132;
  int tid = threadIdx.x;
  size_t m0 = (size_t)blockIdx.x * 128;
  int n0 = blockIdx.y * 128;
  int mr = tid >> 1, hl = tid & 1;
  {
    const float4* src = (const float4*)(x + (m0 + mr) * 128 + hl * 64);
    float4* dst = (float4*)(xs + mr * 132 + hl * 64);
#pragma unroll
    for (int i = 0; i < 16; i++) dst[i] = src[i];
  }
  {
    const float4* src = (const float4*)(wih + (size_t)(n0 + mr) * 128 + hl * 64);
#pragma unroll
    for (int i = 0; i < 16; i++) {
      float4 v = src[i];
      int kb = hl * 64 + i * 4;
      ws[(kb + 0) * 132 + mr] = v.x; ws[(kb + 1) * 132 + mr] = v.y;
      ws[(kb + 2) * 132 + mr] = v.z; ws[(kb + 3) * 132 + mr] = v.w;
    }
  }
  int tx = tid & 15, ty = tid >> 4;
  float bv[8];
#pragma unroll
  for (int j = 0; j < 8; j++) {
    int g = n0 + tx * 8 + j;
    bv[j] = bih[g] + (g < 256 ? bhh[g] : 0.0f);
  }
  __syncthreads();
  float acc[64];
#pragma unroll
  for (int i = 0; i < 8; i++)
#pragma unroll
    for (int j = 0; j < 8; j++) acc[i * 8 + j] = bv[j];
  const float* xrow = xs + ty * 8 * 132;
#pragma unroll 2
  for (int kk = 0; kk < 128; kk += 4) {
    float4 a4[8];
#pragma unroll
    for (int i = 0; i < 8; i++) a4[i] = *(const float4*)(xrow + i * 132 + kk);
#pragma unroll
    for (int dk = 0; dk < 4; dk++) {
      float4 bl = *(const float4*)(ws + (kk + dk) * 132 + tx * 8);
      float4 bh = *(const float4*)(ws + (kk + dk) * 132 + tx * 8 + 4);
#pragma unroll
      for (int i = 0; i < 8; i++) {
        float av = (dk == 0) ? a4[i].x : (dk == 1) ? a4[i].y : (dk == 2) ? a4[i].z : a4[i].w;
        acc[i*8+0] += av * bl.x; acc[i*8+1] += av * bl.y;
        acc[i*8+2] += av * bl.z; acc[i*8+3] += av * bl.w;
        acc[i*8+4] += av * bh.x; acc[i*8+5] += av * bh.y;
        acc[i*8+6] += av * bh.z; acc[i*8+7] += av * bh.w;
      }
    }
  }
#pragma unroll
  for (int i = 0; i < 8; i++) {
    float* dst = g_gi + (m0 + ty * 8 + i) * 384 + n0 + tx * 8;
    *(float4*)(dst)     = make_float4(acc[i*8+0], acc[i*8+1], acc[i*8+2], acc[i*8+3]);
    *(float4*)(dst + 4) = make_float4(acc[i*8+4], acc[i*8+5], acc[i*8+6], acc[i*8+7]);
  }
}

__global__ __launch_bounds__(128) void k_act2(const float* __restrict__ x,
                                              const float* __restrict__ w1,
                                              const float* __restrict__ b1,
                                              const float* __restrict__ w2,
                                              const float* __restrict__ b2) {
  extern __shared__ float sm[];
  float* xs  = sm;
  float* w1s = xs + 128 * 132;
  float* w2s = w1s + 64 * 128;
  float* b1s = w2s + 640;
  float* b2s = b1s + 64;
  int tid = threadIdx.x;
  size_t row0 = (size_t)blockIdx.x * 128;
  const float4* xg = (const float4*)(x + row0 * 128);
  for (int i = tid; i < 128 * 32; i += 128) {
    int r = i >> 5, c = i & 31;
    ((float4*)(xs + r * 132))[c] = xg[i];
  }
  for (int i = tid; i < 64 * 32; i += 128) ((float4*)w1s)[i] = ((const float4*)w1)[i];
  for (int i = tid; i < 640; i += 128) w2s[i] = w2[i];
  if (tid < 64) b1s[tid] = b1[tid];
  if (tid < 10) b2s[tid] = b2[tid];
  __syncthreads();
  float acc[64];
#pragma unroll
  for (int u = 0; u < 64; u++) acc[u] = b1s[u];
  const float4* xr = (const float4*)(xs + tid * 132);
  for (int c = 0; c < 32; c++) {
    float4 xv = xr[c];
#pragma unroll
    for (int u = 0; u < 64; u++) {
      float4 wv = ((const float4*)w1s)[u * 32 + c];
      acc[u] += xv.x * wv.x + xv.y * wv.y + xv.z * wv.z + xv.w * wv.w;
    }
  }
#pragma unroll
  for (int u = 0; u < 64; u++) acc[u] = tanhf(acc[u]);
  size_t row = row0 + tid;
  int b = (int)(row >> 9), t = (int)(row & 511);
  const float* gg = g_gum[2 * t + 1] + b * 10;
  float best = -1e30f; int bi = 0;
#pragma unroll
  for (int a = 0; a < 10; a++) {
    float lg = b2s[a];
#pragma unroll
    for (int u = 0; u < 64; u++) lg += acc[u] * w2s[a * 64 + u];
    float v = lg + gg[a];
    if (v > best) { best = v; bi = a; }
  }
  g_act2[t * 256 + b] = bi;
}

// recurrent v3: 128 CTAs x 512 thr. Wh-ring + f32x2 + n-row-in-regs.
// d = tid&127, q = tid>>7 (k-quarter). Owners tid<256: (bb=q, d).
__global__ __launch_bounds__(512, 1) void k_recur(const int* __restrict__ mask,
                                                  const float* __restrict__ whh,
                                                  const float* __restrict__ bhh,
                                                  const float* __restrict__ a1w1,
                                                  const float* __restrict__ a1b1,
                                                  const float* __restrict__ a1w2,
                                                  const float* __restrict__ a1b2,
                                                  float* __restrict__ out) {
  extern __shared__ float sm[];
  float* wsp  = sm;                   // 256 x 132 (w_hh rows 0..255 = r,z)
  float* hs   = wsp + 256 * 132;      // [2][128] h
  float* ms   = hs + 256;             // [2][128] mean
  float* ps   = ms + 256;             // [512] zarg partials
  float* exch = ps + 512;             // [q4][b2][g3][128] = 3072
  float* ring = exch + 3072;          // [b2][g3][slot10][128] = 7680
  float* w2s  = ring + 7680;          // 640
  float* b1s  = w2s + 640;            // 64
  float* gsm  = b1s + 64;             // [2][20]
  float* bsm  = gsm + 40;             // 12
  int*  asm2  = (int*)(bsm + 12);     // [4]
  int*  ais   = asm2 + 4;             // [4]

  int tid = threadIdx.x;
  int d = tid & 127, q = tid >> 7;
  int wid = tid >> 5, lane = tid & 31;
  int b0 = blockIdx.x * 2;
  int bb = q & 1;
  int bg = b0 + bb;
  bool owner = (tid < 256);
  float* outh = out + (size_t)Bb * 128;

  // w_hh r,z rows into padded smem; n-gate quarter into regs
  for (int i = tid; i < 256 * 128; i += 512)
    wsp[(i >> 7) * 132 + (i & 127)] = whh[i];
  unsigned long long wn[16];
  {
    const unsigned long long* src =
        (const unsigned long long*)(whh + (size_t)(256 + d) * 128 + q * 32);
#pragma unroll
    for (int k = 0; k < 16; k++) wn[k] = src[k];
  }
  for (int i = tid; i < 7680; i += 512) ring[i] = 0.0f;
  for (int i = tid; i < 640; i += 512) w2s[i] = a1w2[i];
  if (tid < 64) b1s[tid] = a1b1[tid];
  if (tid < 10) bsm[tid] = a1b2[tid];

  // zarg weights: thread (u=tid&63, kq=(tid>>6)&3, zb=tid>>8)
  float w1r[32];
  {
    int u = tid & 63, kq = (tid >> 6) & 3;
    const float4* src = (const float4*)(a1w1 + u * 128 + kq * 32);
#pragma unroll
    for (int k = 0; k < 8; k++) {
      float4 v = src[k];
      w1r[4*k] = v.x; w1r[4*k+1] = v.y; w1r[4*k+2] = v.z; w1r[4*k+3] = v.w;
    }
  }
  float bhn = bhh[256 + d];

  float h = 0.0f, buf[10];
#pragma unroll
  for (int s9 = 0; s9 < 10; s9++) buf[s9] = 0.0f;

  if (owner) {
    size_t rr = ((size_t)bg * 512) * 384;
    float gir = g_gi[rr + d], giz = g_gi[rr + 128 + d], gin = g_gi[rr + 256 + d];
    float r = sigm(gir), z = sigm(giz);
    h = (1.0f - z) * tanhf(gin + r * bhn);
    outh[((size_t)bg * 512) * 128 + d] = h;
  }
  if (tid < 20)       gsm[20 + tid] = g_gum[2][(b0 + tid / 10) * 10 + tid % 10];
  else if (tid < 22)  asm2[2 + tid - 20] = g_act2[256 + b0 + (tid - 20)];
  __syncthreads();

  for (int t = 1; t < 512; t++) {
    int cur = t & 1, nxt = cur ^ 1;
    float gir = 0, giz = 0, gin = 0;
    if (owner) {
      size_t rg = ((size_t)bg * 512 + t) * 384;
      gir = g_gi[rg + d]; giz = g_gi[rg + 128 + d]; gin = g_gi[rg + 256 + d];
      float s = h;
#pragma unroll
      for (int s9 = 0; s9 < 9; s9++) { buf[s9] = buf[s9 + 1]; s += buf[s9]; }
      buf[9] = h;
      hs[bb * 128 + d] = h;
      ms[bb * 128 + d] = s * 0.1f;
    }
    __syncthreads();                                  // A
    // GEMV W@h_{t-1} (all threads), f32x2 packed k-pairs
    {
      int k0 = q * 32;
      const ulonglong2* wr2 = (const ulonglong2*)(wsp + d * 132 + k0);
      const ulonglong2* wz2 = (const ulonglong2*)(wsp + (d + 128) * 132 + k0);
      const ulonglong2* va = (const ulonglong2*)(hs + k0);
      const ulonglong2* vb = (const ulonglong2*)(hs + 128 + k0);
      unsigned long long ar0 = 0, az0 = 0, an0 = 0, ar1 = 0, az1 = 0, an1 = 0;
#pragma unroll
      for (int c = 0; c < 8; c++) {
        ulonglong2 v0 = va[c], v1 = vb[c];
        ulonglong2 w0 = wr2[c], w1 = wz2[c];
        f2(ar0, w0.x, v0.x); f2(ar0, w0.y, v0.y);
        f2(ar1, w0.x, v1.x); f2(ar1, w0.y, v1.y);
        f2(az0, w1.x, v0.x); f2(az0, w1.y, v0.y);
        f2(az1, w1.x, v1.x); f2(az1, w1.y, v1.y);
        f2(an0, wn[2*c], v0.x); f2(an0, wn[2*c+1], v0.y);
        f2(an1, wn[2*c], v1.x); f2(an1, wn[2*c+1], v1.y);
      }
      exch[((q * 2 + 0) * 3 + 0) * 128 + d] = hsum(ar0);
      exch[((q * 2 + 0) * 3 + 1) * 128 + d] = hsum(az0);
      exch[((q * 2 + 0) * 3 + 2) * 128 + d] = hsum(an0);
      exch[((q * 2 + 1) * 3 + 0) * 128 + d] = hsum(ar1);
      exch[((q * 2 + 1) * 3 + 1) * 128 + d] = hsum(az1);
      exch[((q * 2 + 1) * 3 + 2) * 128 + d] = hsum(an1);
    }
    // zarg partial (all): obs = mean vector
    {
      int zb = tid >> 8, kq = (tid >> 6) & 3;
      const float4* mv = (const float4*)(ms + zb * 128 + kq * 32);
      float p = 0.0f;
#pragma unroll
      for (int k = 0; k < 8; k++) {
        float4 m = mv[k];
        p += m.x*w1r[4*k] + m.y*w1r[4*k+1] + m.z*w1r[4*k+2] + m.w*w1r[4*k+3];
      }
      ps[tid] = p;
    }
    if (t < 511) {
      if (tid < 20)
        gsm[nxt * 20 + tid] = g_gum[2 * (t + 1)][(b0 + tid / 10) * 10 + tid % 10];
      else if (tid < 22)
        asm2[nxt * 2 + tid - 20] = g_act2[(t + 1) * 256 + b0 + (tid - 20)];
    }
    __syncthreads();                                  // B
    if (wid < 2) {
      // agent-1 logits + argmax (warp wid = batch wid)
      float sA = 0.0f, sB = 0.0f;
#pragma unroll
      for (int kq = 0; kq < 4; kq++) {
        sA += ps[wid * 256 + kq * 64 + lane];
        sB += ps[wid * 256 + kq * 64 + 32 + lane];
      }
      float zA = tanhf(sA + b1s[lane]), zB = tanhf(sB + b1s[lane + 32]);
      float lp[10];
#pragma unroll
      for (int a = 0; a < 10; a++)
        lp[a] = zA * w2s[a * 64 + lane] + zB * w2s[a * 64 + 32 + lane];
#pragma unroll
      for (int off = 16; off > 0; off >>= 1)
#pragma unroll
        for (int a = 0; a < 10; a++) lp[a] += __shfl_down_sync(0xffffffffu, lp[a], off);
      if (lane == 0) {
        float best = -1e30f; int bi = 0;
#pragma unroll
        for (int a = 0; a < 10; a++) {
          float v = lp[a] + bsm[a] + gsm[cur * 20 + wid * 10 + a];
          if (v > best) { best = v; bi = a; }
        }
        ais[wid] = bi; ais[2 + wid] = asm2[cur * 2 + wid];
      }
    } else if (tid >= 256) {
      // ring push (threads 256..511 handle all (bb,d) pairs)
      int pd = tid - 256, pbb = pd >> 7, pdd = pd & 127;
      int p9 = (t - 1) % 10;
#pragma unroll
      for (int g = 0; g < 3; g++) {
        float s = exch[((0 * 2 + pbb) * 3 + g) * 128 + pdd]
                + exch[((1 * 2 + pbb) * 3 + g) * 128 + pdd]
                + exch[((2 * 2 + pbb) * 3 + g) * 128 + pdd]
                + exch[((3 * 2 + pbb) * 3 + g) * 128 + pdd];
        ring[((pbb * 3 + g) * 10 + p9) * 128 + pdd] = s;
      }
    }
    __syncthreads();                                  // C
    if (owner) {
      int aa = ais[bb], a2i = ais[2 + bb];
      int p9 = (t - 1) % 10;
      int s1 = (t + aa) % 10, s2 = (t + a2i) % 10;
      const float* rb = ring + (bb * 3) * 10 * 128 + d;
      float whr = 0.25f * (rb[(0 * 10 + s1) * 128] + rb[(0 * 10 + s2) * 128])
                + 0.5f * rb[(0 * 10 + p9) * 128];
      float whz = 0.25f * (rb[(1 * 10 + s1) * 128] + rb[(1 * 10 + s2) * 128])
                + 0.5f * rb[(1 * 10 + p9) * 128];
      float whn = 0.25f * (rb[(2 * 10 + s1) * 128] + rb[(2 * 10 + s2) * 128])
                + 0.5f * rb[(2 * 10 + p9) * 128];
      float sa = buf[0], sb2 = buf[0];
#pragma unroll
      for (int s9 = 1; s9 < 10; s9++) {
        if (aa == s9) sa = buf[s9];
        if (a2i == s9) sb2 = buf[s9];
      }
      float wtd = 0.25f * (sa + sb2) + 0.5f * h;
      float r = sigm(gir + whr), z = sigm(giz + whz);
      float n = tanhf(gin + r * (whn + bhn));
      h = (1.0f - z) * n + z * wtd;
      outh[((size_t)bg * 512 + t) * 128 + d] = h;
    }
  }

  __syncthreads();
  if (owner) {
    int cnt = 0;
    for (int t2 = d; t2 < 512; t2 += 128) cnt += mask[bg * 512 + t2];
    ps[tid] = (float)cnt;
  }
  __syncthreads();
  if (tid < 2) {
    int s = 0;
    for (int i = 0; i < 128; i++) s += (int)ps[tid * 128 + i];
    ais[tid] = s - 1;
  }
  __syncthreads();
  if (owner) {
    int li = ais[bb];
    out[bg * 128 + d] = outh[((size_t)bg * 512 + li) * 128 + d];
  }
}

extern "C" void kernel_launch(void* const* d_in, const int* in_sizes, int n_in,
                              void* d_out, int out_size) {
  const float* x    = (const float*)d_in[0];
  const int*   mask = (const int*)d_in[1];
  const float* wih  = (const float*)d_in[2];
  const float* whh  = (const float*)d_in[3];
  const float* bih  = (const float*)d_in[4];
  const float* bhh  = (const float*)d_in[5];
  const float* a1w1 = (const float*)d_in[6];
  const float* a1b1 = (const float*)d_in[7];
  const float* a1w2 = (const float*)d_in[8];
  const float* a1b2 = (const float*)d_in[9];
  const float* a2w1 = (const float*)d_in[10];
  const float* a2b1 = (const float*)d_in[11];
  const float* a2w2 = (const float*)d_in[12];
  const float* a2b2 = (const float*)d_in[13];
  float* out = (float*)d_out;

  const int smem_gi = 2 * 128 * 132 * 4;
  const int smem_a2 = (128 * 132 + 64 * 128 + 640 + 64 + 16) * 4;
  const int smem_rc = (256 * 132 + 256 + 256 + 512 + 3072 + 7680 + 640 + 64 + 40 + 12) * 4 + 64;

  cudaFuncSetAttribute(k_gi,    cudaFuncAttributeMaxDynamicSharedMemorySize, smem_gi);
  cudaFuncSetAttribute(k_act2,  cudaFuncAttributeMaxDynamicSharedMemorySize, smem_a2);
  cudaFuncSetAttribute(k_recur, cudaFuncAttributeMaxDynamicSharedMemorySize, smem_rc);

  k_keys<<<4, 256>>>();
  k_gum<<<1024, 256>>>();
  k_act2<<<1024, 128, smem_a2>>>(x, a2w1, a2b1, a2w2, a2b2);
  k_gi<<<dim3(1024, 3), 256, smem_gi>>>(x, wih, bih, bhh);
  k_recur<<<128, 512, smem_rc>>>(mask, whh, bhh, a1w1, a1b1, a1w2, a1b2, out);
}